// round 1
// baseline (speedup 1.0000x reference)
#include <cuda_runtime.h>
#include <math.h>

// Problem constants
#define Bq   4
#define Lq   1024
#define Dq   1280
#define Hq   20
#define HDq  64
#define BH   (Bq*Hq)     // 80
#define LKV  (2*Lq)      // 2048
#define ALPHA 0.48f
#define Mrows (Bq*Lq)    // 4096

// Scratch (device globals; no allocation allowed)
__device__ float g_Q[BH * Lq * HDq];     // [80,1024,64]  20 MB
__device__ float g_K[BH * LKV * HDq];    // [80,2048,64]  40 MB
__device__ float g_V[BH * LKV * HDq];    // [80,2048,64]  40 MB
__device__ float g_ctx[Bq * Lq * Dq];    // [4,1024,1280] 20 MB

// ---------------------------------------------------------------------------
// Fill second half of K/V scratch with ALPHA-scaled context bank
// ---------------------------------------------------------------------------
__global__ void bg_copy_kernel(const float* __restrict__ Kbg,
                               const float* __restrict__ Vbg)
{
    int i = blockIdx.x * blockDim.x + threadIdx.x;
    const int n = BH * Lq * HDq;   // 5,242,880
    if (i >= n) return;
    int head = i / (Lq * HDq);
    int rem  = i - head * (Lq * HDq);
    int dst  = head * (LKV * HDq) + (Lq * HDq) + rem;
    g_K[dst] = ALPHA * Kbg[i];
    g_V[dst] = ALPHA * Vbg[i];
}

// ---------------------------------------------------------------------------
// SIMT GEMM: C[M=4096, N=1280] = A[4096,1280] @ W[1280,1280]
// 128x128 tile, BK=8, 256 threads, 8x8 per thread.
// mode 0: plain output + bias (final projection, writes d_out)
// mode 1/2/3: scatter into g_Q / g_K / g_V head-major layout
// ---------------------------------------------------------------------------
__global__ void gemm128_kernel(const float* __restrict__ A,
                               const float* __restrict__ W,
                               const float* __restrict__ bias,
                               float* __restrict__ C,
                               int mode)
{
    __shared__ float As[8][128];
    __shared__ float Bs[8][128];

    const int tid = threadIdx.x;
    const int bm  = blockIdx.y * 128;
    const int bn  = blockIdx.x * 128;
    const int tx  = tid & 15;         // 0..15
    const int ty  = tid >> 4;         // 0..15

    // load indices
    const int aRow = tid >> 1;        // 0..127
    const int aCol = (tid & 1) << 2;  // 0 or 4
    const int bRow = tid >> 5;        // 0..7
    const int bCol = (tid & 31) << 2; // 0..124

    const float* Ap = A + (size_t)(bm + aRow) * Dq + aCol;
    const float* Bp = W + (size_t)bRow * Dq + bn + bCol;

    float acc[8][8];
#pragma unroll
    for (int i = 0; i < 8; i++)
#pragma unroll
        for (int j = 0; j < 8; j++) acc[i][j] = 0.f;

    for (int kk = 0; kk < Dq; kk += 8) {
        float4 a4 = *(const float4*)(Ap + kk);
        float4 b4 = *(const float4*)(Bp + (size_t)kk * Dq);
        As[aCol + 0][aRow] = a4.x;
        As[aCol + 1][aRow] = a4.y;
        As[aCol + 2][aRow] = a4.z;
        As[aCol + 3][aRow] = a4.w;
        *(float4*)&Bs[bRow][bCol] = b4;
        __syncthreads();

#pragma unroll
        for (int k = 0; k < 8; k++) {
            float ar[8], br[8];
            *(float4*)&ar[0] = *(const float4*)&As[k][ty * 8 + 0];
            *(float4*)&ar[4] = *(const float4*)&As[k][ty * 8 + 4];
            *(float4*)&br[0] = *(const float4*)&Bs[k][tx * 8 + 0];
            *(float4*)&br[4] = *(const float4*)&Bs[k][tx * 8 + 4];
#pragma unroll
            for (int i = 0; i < 8; i++)
#pragma unroll
                for (int j = 0; j < 8; j++)
                    acc[i][j] = fmaf(ar[i], br[j], acc[i][j]);
        }
        __syncthreads();
    }

    // epilogue
#pragma unroll
    for (int i = 0; i < 8; i++) {
        int row = bm + ty * 8 + i;
        int b   = row >> 10;          // /1024
        int l   = row & 1023;
#pragma unroll
        for (int j = 0; j < 8; j++) {
            int col = bn + tx * 8 + j;
            float v = acc[i][j];
            if (mode == 0) {
                C[(size_t)row * Dq + col] = v + bias[col];
            } else {
                int h  = col >> 6;    // /64
                int hd = col & 63;
                if (mode == 1) {
                    g_Q[(((size_t)(b * Hq + h)) * Lq + l) * HDq + hd] = v;
                } else if (mode == 2) {
                    g_K[(((size_t)(b * Hq + h)) * LKV + l) * HDq + hd] = v;
                } else {
                    g_V[(((size_t)(b * Hq + h)) * LKV + l) * HDq + hd] = v;
                }
            }
        }
    }
}

// ---------------------------------------------------------------------------
// Flash attention, fp32. One block = (head, 64-query tile).
// 256 threads as 16x16; each thread owns a 4x4 fragment.
// ---------------------------------------------------------------------------
#define SPAD 65   // 64+1: conflict-free for scalar column reads

__global__ void attn_kernel(float* __restrict__ ctx)
{
    extern __shared__ float sm[];
    float* Qs = sm;                 // [64][65]
    float* Ks = sm + 64 * SPAD;     // [64][65]
    float* Vs = sm + 2 * 64 * SPAD; // [64][65]
    float* Ps = sm + 3 * 64 * SPAD; // [64][65]

    const int head = blockIdx.y;
    const int qt   = blockIdx.x;
    const int tid  = threadIdx.x;
    const int tx   = tid & 15;
    const int ty   = tid >> 4;

    const float* Qp = g_Q + ((size_t)head * Lq + qt * 64) * HDq;
    const float* Kp = g_K + (size_t)head * LKV * HDq;
    const float* Vp = g_V + (size_t)head * LKV * HDq;

    // Load Q tile, pre-scaled by 1/sqrt(HD) = 0.125
    for (int i = tid; i < 1024; i += 256) {      // 1024 float4 chunks
        int r = i >> 4;
        int c = (i & 15) << 2;
        float4 v = *(const float4*)(Qp + r * 64 + c);
        float* d = Qs + r * SPAD + c;
        d[0] = v.x * 0.125f; d[1] = v.y * 0.125f;
        d[2] = v.z * 0.125f; d[3] = v.w * 0.125f;
    }

    float m_i[4], l_i[4], O[4][4];
#pragma unroll
    for (int i = 0; i < 4; i++) {
        m_i[i] = -1e30f;
        l_i[i] = 0.f;
#pragma unroll
        for (int j = 0; j < 4; j++) O[i][j] = 0.f;
    }

    for (int kt = 0; kt < LKV / 64; kt++) {
        __syncthreads();  // previous PV done (and Q load on iter 0)

        // Load K,V tiles
        for (int i = tid; i < 1024; i += 256) {
            int r = i >> 4;
            int c = (i & 15) << 2;
            const float* kp = Kp + (size_t)(kt * 64 + r) * 64 + c;
            const float* vp = Vp + (size_t)(kt * 64 + r) * 64 + c;
            float4 kv = *(const float4*)kp;
            float4 vv = *(const float4*)vp;
            float* dk = Ks + r * SPAD + c;
            float* dv = Vs + r * SPAD + c;
            dk[0] = kv.x; dk[1] = kv.y; dk[2] = kv.z; dk[3] = kv.w;
            dv[0] = vv.x; dv[1] = vv.y; dv[2] = vv.z; dv[3] = vv.w;
        }
        __syncthreads();

        // S = Q K^T (4x4 fragment)
        float s[4][4];
#pragma unroll
        for (int i = 0; i < 4; i++)
#pragma unroll
            for (int j = 0; j < 4; j++) s[i][j] = 0.f;

#pragma unroll 4
        for (int d = 0; d < 64; d++) {
            float q0 = Qs[(ty * 4 + 0) * SPAD + d];
            float q1 = Qs[(ty * 4 + 1) * SPAD + d];
            float q2 = Qs[(ty * 4 + 2) * SPAD + d];
            float q3 = Qs[(ty * 4 + 3) * SPAD + d];
            float k0 = Ks[(tx * 4 + 0) * SPAD + d];
            float k1 = Ks[(tx * 4 + 1) * SPAD + d];
            float k2 = Ks[(tx * 4 + 2) * SPAD + d];
            float k3 = Ks[(tx * 4 + 3) * SPAD + d];
            s[0][0] = fmaf(q0, k0, s[0][0]); s[0][1] = fmaf(q0, k1, s[0][1]);
            s[0][2] = fmaf(q0, k2, s[0][2]); s[0][3] = fmaf(q0, k3, s[0][3]);
            s[1][0] = fmaf(q1, k0, s[1][0]); s[1][1] = fmaf(q1, k1, s[1][1]);
            s[1][2] = fmaf(q1, k2, s[1][2]); s[1][3] = fmaf(q1, k3, s[1][3]);
            s[2][0] = fmaf(q2, k0, s[2][0]); s[2][1] = fmaf(q2, k1, s[2][1]);
            s[2][2] = fmaf(q2, k2, s[2][2]); s[2][3] = fmaf(q2, k3, s[2][3]);
            s[3][0] = fmaf(q3, k0, s[3][0]); s[3][1] = fmaf(q3, k1, s[3][1]);
            s[3][2] = fmaf(q3, k2, s[3][2]); s[3][3] = fmaf(q3, k3, s[3][3]);
        }

        // Online softmax update (row stats across 16 lanes of same ty)
#pragma unroll
        for (int i = 0; i < 4; i++) {
            float rm = s[i][0];
            rm = fmaxf(rm, s[i][1]); rm = fmaxf(rm, s[i][2]); rm = fmaxf(rm, s[i][3]);
#pragma unroll
            for (int msk = 1; msk < 16; msk <<= 1)
                rm = fmaxf(rm, __shfl_xor_sync(0xffffffffu, rm, msk));
            float mnew = fmaxf(m_i[i], rm);

            float rsum = 0.f;
#pragma unroll
            for (int j = 0; j < 4; j++) {
                s[i][j] = __expf(s[i][j] - mnew);
                rsum += s[i][j];
            }
#pragma unroll
            for (int msk = 1; msk < 16; msk <<= 1)
                rsum += __shfl_xor_sync(0xffffffffu, rsum, msk);

            float sc = __expf(m_i[i] - mnew);
            l_i[i] = l_i[i] * sc + rsum;
            m_i[i] = mnew;
#pragma unroll
            for (int j = 0; j < 4; j++) O[i][j] *= sc;

            // stage P
#pragma unroll
            for (int j = 0; j < 4; j++)
                Ps[(ty * 4 + i) * SPAD + tx * 4 + j] = s[i][j];
        }
        __syncthreads();

        // O += P @ V
#pragma unroll 4
        for (int k = 0; k < 64; k++) {
            float p0 = Ps[(ty * 4 + 0) * SPAD + k];
            float p1 = Ps[(ty * 4 + 1) * SPAD + k];
            float p2 = Ps[(ty * 4 + 2) * SPAD + k];
            float p3 = Ps[(ty * 4 + 3) * SPAD + k];
            float v0 = Vs[k * SPAD + tx * 4 + 0];
            float v1 = Vs[k * SPAD + tx * 4 + 1];
            float v2 = Vs[k * SPAD + tx * 4 + 2];
            float v3 = Vs[k * SPAD + tx * 4 + 3];
            O[0][0] = fmaf(p0, v0, O[0][0]); O[0][1] = fmaf(p0, v1, O[0][1]);
            O[0][2] = fmaf(p0, v2, O[0][2]); O[0][3] = fmaf(p0, v3, O[0][3]);
            O[1][0] = fmaf(p1, v0, O[1][0]); O[1][1] = fmaf(p1, v1, O[1][1]);
            O[1][2] = fmaf(p1, v2, O[1][2]); O[1][3] = fmaf(p1, v3, O[1][3]);
            O[2][0] = fmaf(p2, v0, O[2][0]); O[2][1] = fmaf(p2, v1, O[2][1]);
            O[2][2] = fmaf(p2, v2, O[2][2]); O[2][3] = fmaf(p2, v3, O[2][3]);
            O[3][0] = fmaf(p3, v0, O[3][0]); O[3][1] = fmaf(p3, v1, O[3][1]);
            O[3][2] = fmaf(p3, v2, O[3][2]); O[3][3] = fmaf(p3, v3, O[3][3]);
        }
    }

    // Epilogue: normalize + write ctx in [B, L, D] layout
    const int b = head / Hq;
    const int h = head - b * Hq;
#pragma unroll
    for (int i = 0; i < 4; i++) {
        int lrow = qt * 64 + ty * 4 + i;
        float inv = 1.f / l_i[i];
        float* dst = g_ctx + ((size_t)(b * Lq + lrow)) * Dq + h * HDq + tx * 4;
#pragma unroll
        for (int j = 0; j < 4; j++)
            dst[j] = O[i][j] * inv;
    }
}

// ---------------------------------------------------------------------------
// Launch
// ---------------------------------------------------------------------------
extern "C" void kernel_launch(void* const* d_in, const int* in_sizes, int n_in,
                              void* d_out, int out_size)
{
    const float* X   = (const float*)d_in[0];  // hidden_states [4,1024,1280]
    const float* Kbg = (const float*)d_in[1];  // [80,1024,64]
    const float* Vbg = (const float*)d_in[2];  // [80,1024,64]
    const float* Wq  = (const float*)d_in[3];
    const float* Wk  = (const float*)d_in[4];
    const float* Wv  = (const float*)d_in[5];
    const float* Wo  = (const float*)d_in[6];
    const float* bo  = (const float*)d_in[7];
    float* out = (float*)d_out;

    static bool attr_set = false;
    const int attn_smem = 4 * 64 * SPAD * sizeof(float);  // 66560 B
    if (!attr_set) {
        cudaFuncSetAttribute(attn_kernel,
                             cudaFuncAttributeMaxDynamicSharedMemorySize,
                             attn_smem);
        attr_set = true;
    }

    // 1. context bank halves
    {
        int n = BH * Lq * HDq;
        bg_copy_kernel<<<(n + 255) / 256, 256>>>(Kbg, Vbg);
    }

    // 2. QKV projections (scatter into head-major scratch)
    dim3 ggrid(Dq / 128, Mrows / 128);   // (10, 32)
    gemm128_kernel<<<ggrid, 256>>>(X, Wq, nullptr, nullptr, 1);
    gemm128_kernel<<<ggrid, 256>>>(X, Wk, nullptr, nullptr, 2);
    gemm128_kernel<<<ggrid, 256>>>(X, Wv, nullptr, nullptr, 3);

    // 3. attention
    {
        dim3 agrid(Lq / 64, BH);          // (16, 80)
        attn_kernel<<<agrid, 256, attn_smem>>>(g_ctx);
    }

    // 4. output projection + bias
    // g_ctx is a __device__ global: get its generic address via symbol lookup
    // is not graph-safe per-launch; instead use a small helper kernel-side
    // pointer. We can simply pass the device-global through
    // cudaGetSymbolAddress once (host API, not an allocation).
    {
        static float* ctx_ptr = nullptr;
        if (!ctx_ptr) cudaGetSymbolAddress((void**)&ctx_ptr, g_ctx);
        gemm128_kernel<<<ggrid, 256>>>(ctx_ptr, Wo, bo, out, 0);
    }
}

// round 5
// speedup vs baseline: 1.1233x; 1.1233x over previous
#include <cuda_runtime.h>
#include <cuda_bf16.h>
#include <math.h>
#include <stdint.h>

// Problem constants
#define Bq   4
#define Lq   1024
#define Dq   1280
#define Hq   20
#define HDq  64
#define BH   (Bq*Hq)     // 80
#define LKV  (2*Lq)      // 2048
#define ALPHA 0.48f
#define Mrows (Bq*Lq)    // 4096

// Scratch (device globals; no allocation allowed)
__device__ float g_Q[BH * Lq * HDq];
__device__ float g_K[BH * LKV * HDq];
__device__ float g_V[BH * LKV * HDq];
__device__ float g_ctx[Bq * Lq * Dq];

// ---------------------------------------------------------------------------
// mma.sync helpers (sm_80+ PTX, valid on compute_100)
// ---------------------------------------------------------------------------
__device__ __forceinline__ uint32_t smem_u32(const void* p) {
    uint32_t a;
    asm("{ .reg .u64 t; cvta.to.shared.u64 t, %1; cvt.u32.u64 %0, t; }"
        : "=r"(a) : "l"(p));
    return a;
}

__device__ __forceinline__ void ldmx4(uint32_t* r, uint32_t addr) {
    asm volatile("ldmatrix.sync.aligned.m8n8.x4.shared.b16 {%0,%1,%2,%3}, [%4];"
                 : "=r"(r[0]), "=r"(r[1]), "=r"(r[2]), "=r"(r[3]) : "r"(addr));
}
__device__ __forceinline__ void ldmx4t(uint32_t* r, uint32_t addr) {
    asm volatile("ldmatrix.sync.aligned.m8n8.x4.trans.shared.b16 {%0,%1,%2,%3}, [%4];"
                 : "=r"(r[0]), "=r"(r[1]), "=r"(r[2]), "=r"(r[3]) : "r"(addr));
}
__device__ __forceinline__ void mma16816(float* c, const uint32_t* a,
                                         const uint32_t b0, const uint32_t b1) {
    asm volatile(
        "mma.sync.aligned.m16n8k16.row.col.f32.bf16.bf16.f32 "
        "{%0,%1,%2,%3}, {%4,%5,%6,%7}, {%8,%9}, {%0,%1,%2,%3};"
        : "+f"(c[0]), "+f"(c[1]), "+f"(c[2]), "+f"(c[3])
        : "r"(a[0]), "r"(a[1]), "r"(a[2]), "r"(a[3]), "r"(b0), "r"(b1));
}

// ---------------------------------------------------------------------------
// bg copy: fill second half of K/V with ALPHA-scaled context bank
// ---------------------------------------------------------------------------
__global__ void bg_copy_kernel(const float* __restrict__ Kbg,
                               const float* __restrict__ Vbg)
{
    int i = blockIdx.x * blockDim.x + threadIdx.x;
    const int n = BH * Lq * HDq;
    if (i >= n) return;
    int head = i / (Lq * HDq);
    int rem  = i - head * (Lq * HDq);
    int dst  = head * (LKV * HDq) + (Lq * HDq) + rem;
    g_K[dst] = ALPHA * Kbg[i];
    g_V[dst] = ALPHA * Vbg[i];
}

// ---------------------------------------------------------------------------
// bf16 hi/lo split helper: hi = truncate-to-bf16, lo = rn(x - hi)
// ---------------------------------------------------------------------------
__device__ __forceinline__ void cvt_hi_lo(float4 v, uint2& hi, uint2& lo)
{
    uint32_t x0 = __float_as_uint(v.x), x1 = __float_as_uint(v.y);
    uint32_t x2 = __float_as_uint(v.z), x3 = __float_as_uint(v.w);
    hi.x = __byte_perm(x0, x1, 0x7632);
    hi.y = __byte_perm(x2, x3, 0x7632);
    float l0 = v.x - __uint_as_float(x0 & 0xFFFF0000u);
    float l1 = v.y - __uint_as_float(x1 & 0xFFFF0000u);
    float l2 = v.z - __uint_as_float(x2 & 0xFFFF0000u);
    float l3 = v.w - __uint_as_float(x3 & 0xFFFF0000u);
    __nv_bfloat162 lp0 = __floats2bfloat162_rn(l0, l1);
    __nv_bfloat162 lp1 = __floats2bfloat162_rn(l2, l3);
    lo.x = *reinterpret_cast<uint32_t*>(&lp0);
    lo.y = *reinterpret_cast<uint32_t*>(&lp1);
}

// ---------------------------------------------------------------------------
// Tensor-core GEMM via mma.sync (m16n8k16 bf16, 3-term split):
// C[4096,1280] = A[4096,1280] @ W[1280,1280]
// 128x128 tile, BK=32, 8 warps (4m x 2n), warp tile 32x64.
// mode 0: out = C + bias; mode 1/2/3: scatter to g_Q/g_K/g_V head-major
// ---------------------------------------------------------------------------
#define BM 128
#define BN 128
#define BK 32
#define APAD 40    // row pitch (bf16 elems) for A tiles: conflict-free ldmatrix
#define BPAD 136   // row pitch for B tiles

__global__ __launch_bounds__(256)
void gemm_mma_kernel(const float* __restrict__ A, const float* __restrict__ W,
                     const float* __restrict__ bias, float* __restrict__ C,
                     int mode)
{
    __shared__ __align__(16) __nv_bfloat16 Ah[BM * APAD];
    __shared__ __align__(16) __nv_bfloat16 Al[BM * APAD];
    __shared__ __align__(16) __nv_bfloat16 Bh[BK * BPAD];
    __shared__ __align__(16) __nv_bfloat16 Bl[BK * BPAD];

    const int tid    = threadIdx.x;
    const int lane   = tid & 31;
    const int wid    = tid >> 5;
    const int warp_m = wid & 3;     // 0..3 -> 32-row slab
    const int warp_n = wid >> 2;    // 0..1 -> 64-col slab
    const int bm     = blockIdx.y * BM;
    const int bn     = blockIdx.x * BN;

    const uint32_t ah_u = smem_u32(Ah);
    const uint32_t al_u = smem_u32(Al);
    const uint32_t bh_u = smem_u32(Bh);
    const uint32_t bl_u = smem_u32(Bl);

    float acc[2][8][4];
#pragma unroll
    for (int i = 0; i < 2; i++)
#pragma unroll
        for (int j = 0; j < 8; j++)
#pragma unroll
            for (int k = 0; k < 4; k++) acc[i][j][k] = 0.f;

    // prefetch registers for chunk
    float4 a_pf[4], b_pf[4];

    // A loads: 128x32 fp32 tile = 1024 float4; idx -> row=idx>>3, c4=(idx&7)*4
    // B loads: 32x128 fp32 tile = 1024 float4; idx -> row=idx>>5, c4=(idx&31)*4
#pragma unroll
    for (int it = 0; it < 4; it++) {
        int i = it * 256 + tid;
        a_pf[it] = *(const float4*)(A + (size_t)(bm + (i >> 3)) * Dq + ((i & 7) << 2));
        b_pf[it] = *(const float4*)(W + (size_t)(i >> 5) * Dq + bn + ((i & 31) << 2));
    }

    const int NCH = Dq / BK;   // 40
    for (int c = 0; c < NCH; c++) {
        // ---- store prefetched chunk to smem as hi/lo bf16 ----
#pragma unroll
        for (int it = 0; it < 4; it++) {
            int i   = it * 256 + tid;
            int ar  = i >> 3, ac = (i & 7) << 2;
            uint2 hi, lo;
            cvt_hi_lo(a_pf[it], hi, lo);
            *(uint2*)(Ah + ar * APAD + ac) = hi;
            *(uint2*)(Al + ar * APAD + ac) = lo;
            int br = i >> 5, bc = (i & 31) << 2;
            cvt_hi_lo(b_pf[it], hi, lo);
            *(uint2*)(Bh + br * BPAD + bc) = hi;
            *(uint2*)(Bl + br * BPAD + bc) = lo;
        }
        __syncthreads();

        // ---- prefetch next chunk ----
        if (c + 1 < NCH) {
            int kk = (c + 1) * BK;
#pragma unroll
            for (int it = 0; it < 4; it++) {
                int i = it * 256 + tid;
                a_pf[it] = *(const float4*)(A + (size_t)(bm + (i >> 3)) * Dq + kk + ((i & 7) << 2));
                b_pf[it] = *(const float4*)(W + (size_t)(kk + (i >> 5)) * Dq + bn + ((i & 31) << 2));
            }
        }

        // ---- compute: 2 k16 steps ----
#pragma unroll
        for (int ks = 0; ks < 2; ks++) {
            // A fragments (2 m-frags x hi/lo)
            uint32_t afh[2][4], afl[2][4];
#pragma unroll
            for (int mf = 0; mf < 2; mf++) {
                int row = warp_m * 32 + mf * 16 + (lane & 7) + ((lane >> 3) & 1) * 8;
                int col = ks * 16 + (lane >> 4) * 8;
                uint32_t off = (uint32_t)(row * APAD + col) * 2;
                ldmx4(afh[mf], ah_u + off);
                ldmx4(afl[mf], al_u + off);
            }
            // B fragment pairs (4 pairs x hi/lo), then 3-term mma
#pragma unroll
            for (int nfp = 0; nfp < 4; nfp++) {
                int krow = ks * 16 + (lane & 7) + ((lane >> 3) & 1) * 8;
                int ncol = warp_n * 64 + nfp * 16 + (lane >> 4) * 8;
                uint32_t off = (uint32_t)(krow * BPAD + ncol) * 2;
                uint32_t bfh[4], bfl[4];
                ldmx4t(bfh, bh_u + off);
                ldmx4t(bfl, bl_u + off);
#pragma unroll
                for (int mf = 0; mf < 2; mf++) {
                    float* c0 = acc[mf][nfp * 2];
                    float* c1 = acc[mf][nfp * 2 + 1];
                    mma16816(c0, afh[mf], bfh[0], bfh[1]);
                    mma16816(c1, afh[mf], bfh[2], bfh[3]);
                    mma16816(c0, afh[mf], bfl[0], bfl[1]);
                    mma16816(c1, afh[mf], bfl[2], bfl[3]);
                    mma16816(c0, afl[mf], bfh[0], bfh[1]);
                    mma16816(c1, afl[mf], bfh[2], bfh[3]);
                }
            }
        }
        __syncthreads();
    }

    // ---- epilogue: fragment -> global (float2 per half-fragment row) ----
    const int group = lane >> 2;    // 0..7
    const int tg    = lane & 3;     // 0..3
#pragma unroll
    for (int mf = 0; mf < 2; mf++) {
#pragma unroll
        for (int nf = 0; nf < 8; nf++) {
            int col = bn + warp_n * 64 + nf * 8 + tg * 2;
#pragma unroll
            for (int half = 0; half < 2; half++) {
                int row = bm + warp_m * 32 + mf * 16 + group + half * 8;
                float v0 = acc[mf][nf][half * 2];
                float v1 = acc[mf][nf][half * 2 + 1];
                if (mode == 0) {
                    v0 += bias[col];
                    v1 += bias[col + 1];
                    *(float2*)(C + (size_t)row * Dq + col) = make_float2(v0, v1);
                } else {
                    int b  = row >> 10;
                    int l  = row & 1023;
                    int h  = col >> 6;
                    int hd = col & 63;
                    float2 v2 = make_float2(v0, v1);
                    if (mode == 1) {
                        *(float2*)(g_Q + (((size_t)(b * Hq + h)) * Lq + l) * HDq + hd) = v2;
                    } else if (mode == 2) {
                        *(float2*)(g_K + (((size_t)(b * Hq + h)) * LKV + l) * HDq + hd) = v2;
                    } else {
                        *(float2*)(g_V + (((size_t)(b * Hq + h)) * LKV + l) * HDq + hd) = v2;
                    }
                }
            }
        }
    }
}

// ---------------------------------------------------------------------------
// Flash attention, fp32, float4-vectorized shared loads.
// One block = (head, 64-query tile); 256 threads as 16x16; 4x4 per thread.
// ---------------------------------------------------------------------------
#define SPAD 68

__global__ void attn_kernel(float* __restrict__ ctx)
{
    extern __shared__ float smf[];
    float* Qs = smf;
    float* Ks = smf + 64 * SPAD;
    float* Vs = smf + 2 * 64 * SPAD;
    float* Ps = smf + 3 * 64 * SPAD;

    const int head = blockIdx.y;
    const int qt   = blockIdx.x;
    const int tid  = threadIdx.x;
    const int tx   = tid & 15;
    const int ty   = tid >> 4;

    const float* Qp = g_Q + ((size_t)head * Lq + qt * 64) * HDq;
    const float* Kp = g_K + (size_t)head * LKV * HDq;
    const float* Vp = g_V + (size_t)head * LKV * HDq;

    for (int i = tid; i < 1024; i += 256) {
        int r = i >> 4;
        int c = (i & 15) << 2;
        float4 v = *(const float4*)(Qp + r * 64 + c);
        v.x *= 0.125f; v.y *= 0.125f; v.z *= 0.125f; v.w *= 0.125f;
        *(float4*)(Qs + r * SPAD + c) = v;
    }

    float m_i[4], l_i[4], O[4][4];
#pragma unroll
    for (int i = 0; i < 4; i++) {
        m_i[i] = -1e30f;
        l_i[i] = 0.f;
#pragma unroll
        for (int j = 0; j < 4; j++) O[i][j] = 0.f;
    }

    for (int kt = 0; kt < LKV / 64; kt++) {
        __syncthreads();

        for (int i = tid; i < 1024; i += 256) {
            int r = i >> 4;
            int c = (i & 15) << 2;
            const float* kp = Kp + (size_t)(kt * 64 + r) * 64 + c;
            const float* vp = Vp + (size_t)(kt * 64 + r) * 64 + c;
            *(float4*)(Ks + r * SPAD + c) = *(const float4*)kp;
            *(float4*)(Vs + r * SPAD + c) = *(const float4*)vp;
        }
        __syncthreads();

        float s[4][4];
#pragma unroll
        for (int i = 0; i < 4; i++)
#pragma unroll
            for (int j = 0; j < 4; j++) s[i][j] = 0.f;

#pragma unroll 4
        for (int d4 = 0; d4 < 64; d4 += 4) {
            float4 qv[4], kv[4];
#pragma unroll
            for (int i = 0; i < 4; i++)
                qv[i] = *(const float4*)(Qs + (ty * 4 + i) * SPAD + d4);
#pragma unroll
            for (int j = 0; j < 4; j++)
                kv[j] = *(const float4*)(Ks + (tx * 4 + j) * SPAD + d4);
#pragma unroll
            for (int i = 0; i < 4; i++)
#pragma unroll
                for (int j = 0; j < 4; j++) {
                    s[i][j] = fmaf(qv[i].x, kv[j].x, s[i][j]);
                    s[i][j] = fmaf(qv[i].y, kv[j].y, s[i][j]);
                    s[i][j] = fmaf(qv[i].z, kv[j].z, s[i][j]);
                    s[i][j] = fmaf(qv[i].w, kv[j].w, s[i][j]);
                }
        }

#pragma unroll
        for (int i = 0; i < 4; i++) {
            float rm = s[i][0];
            rm = fmaxf(rm, s[i][1]); rm = fmaxf(rm, s[i][2]); rm = fmaxf(rm, s[i][3]);
#pragma unroll
            for (int msk = 1; msk < 16; msk <<= 1)
                rm = fmaxf(rm, __shfl_xor_sync(0xffffffffu, rm, msk));
            float mnew = fmaxf(m_i[i], rm);

            float rsum = 0.f;
#pragma unroll
            for (int j = 0; j < 4; j++) {
                s[i][j] = __expf(s[i][j] - mnew);
                rsum += s[i][j];
            }
#pragma unroll
            for (int msk = 1; msk < 16; msk <<= 1)
                rsum += __shfl_xor_sync(0xffffffffu, rsum, msk);

            float sc = __expf(m_i[i] - mnew);
            l_i[i] = l_i[i] * sc + rsum;
            m_i[i] = mnew;
#pragma unroll
            for (int j = 0; j < 4; j++) O[i][j] *= sc;

            *(float4*)(Ps + (ty * 4 + i) * SPAD + tx * 4) =
                make_float4(s[i][0], s[i][1], s[i][2], s[i][3]);
        }
        __syncthreads();

#pragma unroll 4
        for (int k = 0; k < 64; k++) {
            float4 vv = *(const float4*)(Vs + k * SPAD + tx * 4);
            float p0 = Ps[(ty * 4 + 0) * SPAD + k];
            float p1 = Ps[(ty * 4 + 1) * SPAD + k];
            float p2 = Ps[(ty * 4 + 2) * SPAD + k];
            float p3 = Ps[(ty * 4 + 3) * SPAD + k];
            O[0][0] = fmaf(p0, vv.x, O[0][0]); O[0][1] = fmaf(p0, vv.y, O[0][1]);
            O[0][2] = fmaf(p0, vv.z, O[0][2]); O[0][3] = fmaf(p0, vv.w, O[0][3]);
            O[1][0] = fmaf(p1, vv.x, O[1][0]); O[1][1] = fmaf(p1, vv.y, O[1][1]);
            O[1][2] = fmaf(p1, vv.z, O[1][2]); O[1][3] = fmaf(p1, vv.w, O[1][3]);
            O[2][0] = fmaf(p2, vv.x, O[2][0]); O[2][1] = fmaf(p2, vv.y, O[2][1]);
            O[2][2] = fmaf(p2, vv.z, O[2][2]); O[2][3] = fmaf(p2, vv.w, O[2][3]);
            O[3][0] = fmaf(p3, vv.x, O[3][0]); O[3][1] = fmaf(p3, vv.y, O[3][1]);
            O[3][2] = fmaf(p3, vv.z, O[3][2]); O[3][3] = fmaf(p3, vv.w, O[3][3]);
        }
    }

    const int b = head / Hq;
    const int h = head - b * Hq;
#pragma unroll
    for (int i = 0; i < 4; i++) {
        int lrow = qt * 64 + ty * 4 + i;
        float inv = 1.f / l_i[i];
        float* dst = g_ctx + ((size_t)(b * Lq + lrow)) * Dq + h * HDq + tx * 4;
        *(float4*)dst = make_float4(O[i][0] * inv, O[i][1] * inv,
                                    O[i][2] * inv, O[i][3] * inv);
    }
}

// ---------------------------------------------------------------------------
// Launch
// ---------------------------------------------------------------------------
extern "C" void kernel_launch(void* const* d_in, const int* in_sizes, int n_in,
                              void* d_out, int out_size)
{
    const float* X   = (const float*)d_in[0];
    const float* Kbg = (const float*)d_in[1];
    const float* Vbg = (const float*)d_in[2];
    const float* Wq  = (const float*)d_in[3];
    const float* Wk  = (const float*)d_in[4];
    const float* Wv  = (const float*)d_in[5];
    const float* Wo  = (const float*)d_in[6];
    const float* bo  = (const float*)d_in[7];
    float* out = (float*)d_out;

    const int attn_smem = 4 * 64 * SPAD * sizeof(float);  // 69632
    static bool attr_set = false;
    static float* ctx_ptr = nullptr;
    if (!attr_set) {
        cudaFuncSetAttribute(attn_kernel,
                             cudaFuncAttributeMaxDynamicSharedMemorySize, attn_smem);
        cudaGetSymbolAddress((void**)&ctx_ptr, g_ctx);
        attr_set = true;
    }

    {
        int n = BH * Lq * HDq;
        bg_copy_kernel<<<(n + 255) / 256, 256>>>(Kbg, Vbg);
    }

    dim3 ggrid(Dq / BN, Mrows / BM);   // (10, 32)
    gemm_mma_kernel<<<ggrid, 256>>>(X, Wq, nullptr, nullptr, 1);
    gemm_mma_kernel<<<ggrid, 256>>>(X, Wk, nullptr, nullptr, 2);
    gemm_mma_kernel<<<ggrid, 256>>>(X, Wv, nullptr, nullptr, 3);

    {
        dim3 agrid(Lq / 64, BH);        // (16, 80)
        attn_kernel<<<agrid, 256, attn_smem>>>(g_ctx);
    }

    gemm_mma_kernel<<<ggrid, 256>>>(ctx_ptr, Wo, bo, out, 0);
}

// round 7
// speedup vs baseline: 3.0375x; 2.7040x over previous
#include <cuda_runtime.h>
#include <cuda_bf16.h>
#include <math.h>
#include <stdint.h>

// Problem constants
#define Bq   4
#define Lq   1024
#define Dq   1280
#define Hq   20
#define HDq  64
#define BH   (Bq*Hq)     // 80
#define LKV  (2*Lq)      // 2048
#define ALPHA 0.48f
#define Mrows (Bq*Lq)    // 4096

// Scratch (device globals; no allocation allowed)
__device__ float g_Q[BH * Lq * HDq];
__device__ float g_K[BH * LKV * HDq];
__device__ float g_V[BH * LKV * HDq];
__device__ float g_ctx[Bq * Lq * Dq];

// ---------------------------------------------------------------------------
// mma.sync helpers (sm_80+ PTX, valid on compute_100)
// ---------------------------------------------------------------------------
__device__ __forceinline__ uint32_t smem_u32(const void* p) {
    uint32_t a;
    asm("{ .reg .u64 t; cvta.to.shared.u64 t, %1; cvt.u32.u64 %0, t; }"
        : "=r"(a) : "l"(p));
    return a;
}
__device__ __forceinline__ void ldmx4(uint32_t* r, uint32_t addr) {
    asm volatile("ldmatrix.sync.aligned.m8n8.x4.shared.b16 {%0,%1,%2,%3}, [%4];"
                 : "=r"(r[0]), "=r"(r[1]), "=r"(r[2]), "=r"(r[3]) : "r"(addr));
}
__device__ __forceinline__ void ldmx4t(uint32_t* r, uint32_t addr) {
    asm volatile("ldmatrix.sync.aligned.m8n8.x4.trans.shared.b16 {%0,%1,%2,%3}, [%4];"
                 : "=r"(r[0]), "=r"(r[1]), "=r"(r[2]), "=r"(r[3]) : "r"(addr));
}
__device__ __forceinline__ void mma16816(float* c, const uint32_t* a,
                                         const uint32_t b0, const uint32_t b1) {
    asm volatile(
        "mma.sync.aligned.m16n8k16.row.col.f32.bf16.bf16.f32 "
        "{%0,%1,%2,%3}, {%4,%5,%6,%7}, {%8,%9}, {%0,%1,%2,%3};"
        : "+f"(c[0]), "+f"(c[1]), "+f"(c[2]), "+f"(c[3])
        : "r"(a[0]), "r"(a[1]), "r"(a[2]), "r"(a[3]), "r"(b0), "r"(b1));
}

// ---------------------------------------------------------------------------
// bg copy
// ---------------------------------------------------------------------------
__global__ void bg_copy_kernel(const float* __restrict__ Kbg,
                               const float* __restrict__ Vbg)
{
    int i = blockIdx.x * blockDim.x + threadIdx.x;
    const int n = BH * Lq * HDq;
    if (i >= n) return;
    int head = i / (Lq * HDq);
    int rem  = i - head * (Lq * HDq);
    int dst  = head * (LKV * HDq) + (Lq * HDq) + rem;
    g_K[dst] = ALPHA * Kbg[i];
    g_V[dst] = ALPHA * Vbg[i];
}

// ---------------------------------------------------------------------------
// hi/lo split helpers
// ---------------------------------------------------------------------------
__device__ __forceinline__ void cvt_hi_lo(float4 v, uint2& hi, uint2& lo)
{
    uint32_t x0 = __float_as_uint(v.x), x1 = __float_as_uint(v.y);
    uint32_t x2 = __float_as_uint(v.z), x3 = __float_as_uint(v.w);
    hi.x = __byte_perm(x0, x1, 0x7632);
    hi.y = __byte_perm(x2, x3, 0x7632);
    float l0 = v.x - __uint_as_float(x0 & 0xFFFF0000u);
    float l1 = v.y - __uint_as_float(x1 & 0xFFFF0000u);
    float l2 = v.z - __uint_as_float(x2 & 0xFFFF0000u);
    float l3 = v.w - __uint_as_float(x3 & 0xFFFF0000u);
    __nv_bfloat162 lp0 = __floats2bfloat162_rn(l0, l1);
    __nv_bfloat162 lp1 = __floats2bfloat162_rn(l2, l3);
    lo.x = *reinterpret_cast<uint32_t*>(&lp0);
    lo.y = *reinterpret_cast<uint32_t*>(&lp1);
}
__device__ __forceinline__ void pack_hi_lo(float x, float y, uint32_t& hi, uint32_t& lo)
{
    uint32_t xb = __float_as_uint(x), yb = __float_as_uint(y);
    hi = __byte_perm(xb, yb, 0x7632);
    float xl = x - __uint_as_float(xb & 0xFFFF0000u);
    float yl = y - __uint_as_float(yb & 0xFFFF0000u);
    __nv_bfloat162 t = __floats2bfloat162_rn(xl, yl);
    lo = *reinterpret_cast<uint32_t*>(&t);
}

// ---------------------------------------------------------------------------
// Tensor-core GEMM via mma.sync (passing round-5 version; loop unroll pinned)
// ---------------------------------------------------------------------------
#define BM 128
#define BN 128
#define BK 32
#define APAD 40
#define BPAD 136

__global__ __launch_bounds__(256)
void gemm_mma_kernel(const float* __restrict__ A, const float* __restrict__ W,
                     const float* __restrict__ bias, float* __restrict__ C,
                     int mode)
{
    __shared__ __align__(16) __nv_bfloat16 Ah[BM * APAD];
    __shared__ __align__(16) __nv_bfloat16 Al[BM * APAD];
    __shared__ __align__(16) __nv_bfloat16 Bh[BK * BPAD];
    __shared__ __align__(16) __nv_bfloat16 Bl[BK * BPAD];

    const int tid    = threadIdx.x;
    const int lane   = tid & 31;
    const int wid    = tid >> 5;
    const int warp_m = wid & 3;
    const int warp_n = wid >> 2;
    const int bm     = blockIdx.y * BM;
    const int bn     = blockIdx.x * BN;

    const uint32_t ah_u = smem_u32(Ah);
    const uint32_t al_u = smem_u32(Al);
    const uint32_t bh_u = smem_u32(Bh);
    const uint32_t bl_u = smem_u32(Bl);

    float acc[2][8][4];
#pragma unroll
    for (int i = 0; i < 2; i++)
#pragma unroll
        for (int j = 0; j < 8; j++)
#pragma unroll
            for (int k = 0; k < 4; k++) acc[i][j][k] = 0.f;

    float4 a_pf[4], b_pf[4];
#pragma unroll
    for (int it = 0; it < 4; it++) {
        int i = it * 256 + tid;
        a_pf[it] = *(const float4*)(A + (size_t)(bm + (i >> 3)) * Dq + ((i & 7) << 2));
        b_pf[it] = *(const float4*)(W + (size_t)(i >> 5) * Dq + bn + ((i & 31) << 2));
    }

    const int NCH = Dq / BK;   // 40
#pragma unroll 1
    for (int c = 0; c < NCH; c++) {
#pragma unroll
        for (int it = 0; it < 4; it++) {
            int i   = it * 256 + tid;
            int ar  = i >> 3, ac = (i & 7) << 2;
            uint2 hi, lo;
            cvt_hi_lo(a_pf[it], hi, lo);
            *(uint2*)(Ah + ar * APAD + ac) = hi;
            *(uint2*)(Al + ar * APAD + ac) = lo;
            int br = i >> 5, bc = (i & 31) << 2;
            cvt_hi_lo(b_pf[it], hi, lo);
            *(uint2*)(Bh + br * BPAD + bc) = hi;
            *(uint2*)(Bl + br * BPAD + bc) = lo;
        }
        __syncthreads();

        if (c + 1 < NCH) {
            int kk = (c + 1) * BK;
#pragma unroll
            for (int it = 0; it < 4; it++) {
                int i = it * 256 + tid;
                a_pf[it] = *(const float4*)(A + (size_t)(bm + (i >> 3)) * Dq + kk + ((i & 7) << 2));
                b_pf[it] = *(const float4*)(W + (size_t)(kk + (i >> 5)) * Dq + bn + ((i & 31) << 2));
            }
        }

#pragma unroll
        for (int ks = 0; ks < 2; ks++) {
            uint32_t afh[2][4], afl[2][4];
#pragma unroll
            for (int mf = 0; mf < 2; mf++) {
                int row = warp_m * 32 + mf * 16 + (lane & 7) + ((lane >> 3) & 1) * 8;
                int col = ks * 16 + (lane >> 4) * 8;
                uint32_t off = (uint32_t)(row * APAD + col) * 2;
                ldmx4(afh[mf], ah_u + off);
                ldmx4(afl[mf], al_u + off);
            }
#pragma unroll
            for (int nfp = 0; nfp < 4; nfp++) {
                int krow = ks * 16 + (lane & 7) + ((lane >> 3) & 1) * 8;
                int ncol = warp_n * 64 + nfp * 16 + (lane >> 4) * 8;
                uint32_t off = (uint32_t)(krow * BPAD + ncol) * 2;
                uint32_t bfh[4], bfl[4];
                ldmx4t(bfh, bh_u + off);
                ldmx4t(bfl, bl_u + off);
#pragma unroll
                for (int mf = 0; mf < 2; mf++) {
                    float* c0 = acc[mf][nfp * 2];
                    float* c1 = acc[mf][nfp * 2 + 1];
                    mma16816(c0, afh[mf], bfh[0], bfh[1]);
                    mma16816(c1, afh[mf], bfh[2], bfh[3]);
                    mma16816(c0, afh[mf], bfl[0], bfl[1]);
                    mma16816(c1, afh[mf], bfl[2], bfl[3]);
                    mma16816(c0, afl[mf], bfh[0], bfh[1]);
                    mma16816(c1, afl[mf], bfh[2], bfh[3]);
                }
            }
        }
        __syncthreads();
    }

    const int group = lane >> 2;
    const int tg    = lane & 3;
#pragma unroll
    for (int mf = 0; mf < 2; mf++) {
#pragma unroll
        for (int nf = 0; nf < 8; nf++) {
            int col = bn + warp_n * 64 + nf * 8 + tg * 2;
#pragma unroll
            for (int half = 0; half < 2; half++) {
                int row = bm + warp_m * 32 + mf * 16 + group + half * 8;
                float v0 = acc[mf][nf][half * 2];
                float v1 = acc[mf][nf][half * 2 + 1];
                if (mode == 0) {
                    v0 += bias[col];
                    v1 += bias[col + 1];
                    *(float2*)(C + (size_t)row * Dq + col) = make_float2(v0, v1);
                } else {
                    int b  = row >> 10;
                    int l  = row & 1023;
                    int h  = col >> 6;
                    int hd = col & 63;
                    float2 v2 = make_float2(v0, v1);
                    if (mode == 1) {
                        *(float2*)(g_Q + (((size_t)(b * Hq + h)) * Lq + l) * HDq + hd) = v2;
                    } else if (mode == 2) {
                        *(float2*)(g_K + (((size_t)(b * Hq + h)) * LKV + l) * HDq + hd) = v2;
                    } else {
                        *(float2*)(g_V + (((size_t)(b * Hq + h)) * LKV + l) * HDq + hd) = v2;
                    }
                }
            }
        }
    }
}

// ---------------------------------------------------------------------------
// Tensor-core flash attention (mma.sync bf16, 3-term split, register softmax)
// Block = 128 queries (8 warps x 16 rows), full 64-dim head per warp.
// Grid = (Lq/128, BH) = (8, 80).
// ---------------------------------------------------------------------------
#define PITCH 72   // bf16 row pitch for 64-wide tiles (conflict-free ldmatrix)

__global__ __launch_bounds__(256)
void attn_mma_kernel()
{
    __shared__ __align__(16) __nv_bfloat16 sm_t[4 * 64 * PITCH];  // 36,864 B

    const int head = blockIdx.y;
    const int qb   = blockIdx.x * 128;
    const int tid  = threadIdx.x;
    const int lane = tid & 31;
    const int warp = tid >> 5;

    // Views: Q staging overlays the K/V region (used only in prologue)
    __nv_bfloat16* Qh_s = sm_t;
    __nv_bfloat16* Ql_s = sm_t + 128 * PITCH;
    __nv_bfloat16* Kh_s = sm_t;
    __nv_bfloat16* Kl_s = sm_t + 64 * PITCH;
    __nv_bfloat16* Vh_s = sm_t + 2 * 64 * PITCH;
    __nv_bfloat16* Vl_s = sm_t + 3 * 64 * PITCH;
    const uint32_t qh_u = smem_u32(Qh_s);
    const uint32_t ql_u = smem_u32(Ql_s);
    const uint32_t kh_u = smem_u32(Kh_s);
    const uint32_t kl_u = smem_u32(Kl_s);
    const uint32_t vh_u = smem_u32(Vh_s);
    const uint32_t vl_u = smem_u32(Vl_s);

    // ---- Prologue: stage Q (scaled by 0.125) as hi/lo bf16, grab fragments ----
    const float* Qp = g_Q + ((size_t)head * Lq + qb) * HDq;
#pragma unroll
    for (int it = 0; it < 8; it++) {
        int i  = it * 256 + tid;       // 0..2047 float4 units (128x64 fp32)
        int r  = i >> 4;
        int c4 = (i & 15) << 2;
        float4 v = *(const float4*)(Qp + r * 64 + c4);
        v.x *= 0.125f; v.y *= 0.125f; v.z *= 0.125f; v.w *= 0.125f;
        uint2 hi, lo;
        cvt_hi_lo(v, hi, lo);
        *(uint2*)(Qh_s + r * PITCH + c4) = hi;
        *(uint2*)(Ql_s + r * PITCH + c4) = lo;
    }
    __syncthreads();

    uint32_t qfh[4][4], qfl[4][4];
    {
        int arow = warp * 16 + (lane & 7) + ((lane >> 3) & 1) * 8;
#pragma unroll
        for (int ks = 0; ks < 4; ks++) {
            uint32_t off = (uint32_t)(arow * PITCH + ks * 16 + (lane >> 4) * 8) * 2;
            ldmx4(qfh[ks], qh_u + off);
            ldmx4(qfl[ks], ql_u + off);
        }
    }
    __syncthreads();   // Q staging can now be overwritten by K/V

    // ---- State ----
    float O[8][4];
#pragma unroll
    for (int i = 0; i < 8; i++)
#pragma unroll
        for (int j = 0; j < 4; j++) O[i][j] = 0.f;
    float m_r[2] = {-1e30f, -1e30f};
    float l_r[2] = {0.f, 0.f};

    const float* Kp = g_K + (size_t)head * LKV * HDq;
    const float* Vp = g_V + (size_t)head * LKV * HDq;

    // Preload tile 0 into registers
    float4 kpf[4], vpf[4];
#pragma unroll
    for (int it = 0; it < 4; it++) {
        int i  = it * 256 + tid;       // 0..1023 float4 units (64x64 fp32)
        int r  = i >> 4;
        int c4 = (i & 15) << 2;
        kpf[it] = *(const float4*)(Kp + (size_t)r * 64 + c4);
        vpf[it] = *(const float4*)(Vp + (size_t)r * 64 + c4);
    }

    const int NKT = LKV / 64;   // 32
#pragma unroll 1
    for (int kt = 0; kt < NKT; kt++) {
        // ---- store staged K/V tile (hi/lo) ----
#pragma unroll
        for (int it = 0; it < 4; it++) {
            int i  = it * 256 + tid;
            int r  = i >> 4;
            int c4 = (i & 15) << 2;
            uint2 hi, lo;
            cvt_hi_lo(kpf[it], hi, lo);
            *(uint2*)(Kh_s + r * PITCH + c4) = hi;
            *(uint2*)(Kl_s + r * PITCH + c4) = lo;
            cvt_hi_lo(vpf[it], hi, lo);
            *(uint2*)(Vh_s + r * PITCH + c4) = hi;
            *(uint2*)(Vl_s + r * PITCH + c4) = lo;
        }
        __syncthreads();

        // ---- prefetch next tile ----
        if (kt + 1 < NKT) {
            const float* kn = Kp + (size_t)(kt + 1) * 64 * 64;
            const float* vn = Vp + (size_t)(kt + 1) * 64 * 64;
#pragma unroll
            for (int it = 0; it < 4; it++) {
                int i  = it * 256 + tid;
                int r  = i >> 4;
                int c4 = (i & 15) << 2;
                kpf[it] = *(const float4*)(kn + (size_t)r * 64 + c4);
                vpf[it] = *(const float4*)(vn + (size_t)r * 64 + c4);
            }
        }

        // ---- S = Q K^T (3-term) ----
        float c[8][4];
#pragma unroll
        for (int i = 0; i < 8; i++)
#pragma unroll
            for (int j = 0; j < 4; j++) c[i][j] = 0.f;

#pragma unroll
        for (int ks = 0; ks < 4; ks++) {            // dim k16 steps
#pragma unroll
            for (int n16 = 0; n16 < 4; n16++) {     // key n16 groups
                int nrow = n16 * 16 + (lane & 7) + (lane >> 4) * 8;
                int kcol = ks * 16 + ((lane >> 3) & 1) * 8;
                uint32_t off = (uint32_t)(nrow * PITCH + kcol) * 2;
                uint32_t kh[4], kl[4];
                ldmx4(kh, kh_u + off);
                ldmx4(kl, kl_u + off);
                float* c0 = c[n16 * 2];
                float* c1 = c[n16 * 2 + 1];
                mma16816(c0, qfh[ks], kh[0], kh[1]);
                mma16816(c1, qfh[ks], kh[2], kh[3]);
                mma16816(c0, qfh[ks], kl[0], kl[1]);
                mma16816(c1, qfh[ks], kl[2], kl[3]);
                mma16816(c0, qfl[ks], kh[0], kh[1]);
                mma16816(c1, qfl[ks], kh[2], kh[3]);
            }
        }

        // ---- online softmax in fragment registers ----
#pragma unroll
        for (int h = 0; h < 2; h++) {
            float rm = c[0][2 * h];
#pragma unroll
            for (int nf = 0; nf < 8; nf++) {
                rm = fmaxf(rm, c[nf][2 * h]);
                rm = fmaxf(rm, c[nf][2 * h + 1]);
            }
            rm = fmaxf(rm, __shfl_xor_sync(0xffffffffu, rm, 1));
            rm = fmaxf(rm, __shfl_xor_sync(0xffffffffu, rm, 2));
            float mnew  = fmaxf(m_r[h], rm);
            float alpha = __expf(m_r[h] - mnew);
            float sum = 0.f;
#pragma unroll
            for (int nf = 0; nf < 8; nf++) {
                c[nf][2 * h]     = __expf(c[nf][2 * h] - mnew);
                c[nf][2 * h + 1] = __expf(c[nf][2 * h + 1] - mnew);
                sum += c[nf][2 * h] + c[nf][2 * h + 1];
            }
            sum += __shfl_xor_sync(0xffffffffu, sum, 1);
            sum += __shfl_xor_sync(0xffffffffu, sum, 2);
            l_r[h] = l_r[h] * alpha + sum;
            m_r[h] = mnew;
#pragma unroll
            for (int nf = 0; nf < 8; nf++) {
                O[nf][2 * h]     *= alpha;
                O[nf][2 * h + 1] *= alpha;
            }
        }

        // ---- O += P V (3-term), P packed from S fragments ----
#pragma unroll
        for (int ks = 0; ks < 4; ks++) {            // key k16 steps
            uint32_t ph[4], pl[4];
            pack_hi_lo(c[2 * ks][0],     c[2 * ks][1],     ph[0], pl[0]);
            pack_hi_lo(c[2 * ks][2],     c[2 * ks][3],     ph[1], pl[1]);
            pack_hi_lo(c[2 * ks + 1][0], c[2 * ks + 1][1], ph[2], pl[2]);
            pack_hi_lo(c[2 * ks + 1][2], c[2 * ks + 1][3], ph[3], pl[3]);
#pragma unroll
            for (int nfp = 0; nfp < 4; nfp++) {     // dim n16 groups
                int krow = ks * 16 + (lane & 7) + ((lane >> 3) & 1) * 8;
                int ncol = nfp * 16 + (lane >> 4) * 8;
                uint32_t off = (uint32_t)(krow * PITCH + ncol) * 2;
                uint32_t vh[4], vl[4];
                ldmx4t(vh, vh_u + off);
                ldmx4t(vl, vl_u + off);
                float* o0 = O[nfp * 2];
                float* o1 = O[nfp * 2 + 1];
                mma16816(o0, ph, vh[0], vh[1]);
                mma16816(o1, ph, vh[2], vh[3]);
                mma16816(o0, ph, vl[0], vl[1]);
                mma16816(o1, ph, vl[2], vl[3]);
                mma16816(o0, pl, vh[0], vh[1]);
                mma16816(o1, pl, vh[2], vh[3]);
            }
        }
        __syncthreads();   // all smem reads done before next tile's stores
    }

    // ---- epilogue ----
    const int b = head / Hq;
    const int h = head - b * Hq;
    const int group = lane >> 2;
    const int tg    = lane & 3;
    float inv0 = 1.f / l_r[0];
    float inv1 = 1.f / l_r[1];
    int row0 = qb + warp * 16 + group;
    int row1 = row0 + 8;
#pragma unroll
    for (int nf = 0; nf < 8; nf++) {
        int col = h * HDq + nf * 8 + tg * 2;
        *(float2*)(g_ctx + (size_t)(b * Lq + row0) * Dq + col) =
            make_float2(O[nf][0] * inv0, O[nf][1] * inv0);
        *(float2*)(g_ctx + (size_t)(b * Lq + row1) * Dq + col) =
            make_float2(O[nf][2] * inv1, O[nf][3] * inv1);
    }
}

// ---------------------------------------------------------------------------
// Launch
// ---------------------------------------------------------------------------
extern "C" void kernel_launch(void* const* d_in, const int* in_sizes, int n_in,
                              void* d_out, int out_size)
{
    const float* X   = (const float*)d_in[0];
    const float* Kbg = (const float*)d_in[1];
    const float* Vbg = (const float*)d_in[2];
    const float* Wq  = (const float*)d_in[3];
    const float* Wk  = (const float*)d_in[4];
    const float* Wv  = (const float*)d_in[5];
    const float* Wo  = (const float*)d_in[6];
    const float* bo  = (const float*)d_in[7];
    float* out = (float*)d_out;

    static bool init_done = false;
    static float* ctx_ptr = nullptr;
    if (!init_done) {
        cudaGetSymbolAddress((void**)&ctx_ptr, g_ctx);
        init_done = true;
    }

    {
        int n = BH * Lq * HDq;
        bg_copy_kernel<<<(n + 255) / 256, 256>>>(Kbg, Vbg);
    }

    dim3 ggrid(Dq / BN, Mrows / BM);   // (10, 32)
    gemm_mma_kernel<<<ggrid, 256>>>(X, Wq, nullptr, nullptr, 1);
    gemm_mma_kernel<<<ggrid, 256>>>(X, Wk, nullptr, nullptr, 2);
    gemm_mma_kernel<<<ggrid, 256>>>(X, Wv, nullptr, nullptr, 3);

    {
        dim3 agrid(Lq / 128, BH);       // (8, 80)
        attn_mma_kernel<<<agrid, 256>>>();
    }

    gemm_mma_kernel<<<ggrid, 256>>>(ctx_ptr, Wo, bo, out, 0);
}

// round 8
// speedup vs baseline: 3.4722x; 1.1431x over previous
#include <cuda_runtime.h>
#include <cuda_bf16.h>
#include <math.h>
#include <stdint.h>

// Problem constants
#define Bq   4
#define Lq   1024
#define Dq   1280
#define Hq   20
#define HDq  64
#define BH   (Bq*Hq)     // 80
#define LKV  (2*Lq)      // 2048
#define ALPHA 0.48f
#define Mrows (Bq*Lq)    // 4096

// Scratch (device globals; no allocation allowed)
__device__ float g_Q[BH * Lq * HDq];
__device__ float g_K[BH * LKV * HDq];
__device__ float g_V[BH * LKV * HDq];
__device__ float g_ctx[Bq * Lq * Dq];

// ---------------------------------------------------------------------------
// mma.sync helpers (sm_80+ PTX, valid on compute_100)
// ---------------------------------------------------------------------------
__device__ __forceinline__ uint32_t smem_u32(const void* p) {
    uint32_t a;
    asm("{ .reg .u64 t; cvta.to.shared.u64 t, %1; cvt.u32.u64 %0, t; }"
        : "=r"(a) : "l"(p));
    return a;
}
__device__ __forceinline__ void ldmx4(uint32_t* r, uint32_t addr) {
    asm volatile("ldmatrix.sync.aligned.m8n8.x4.shared.b16 {%0,%1,%2,%3}, [%4];"
                 : "=r"(r[0]), "=r"(r[1]), "=r"(r[2]), "=r"(r[3]) : "r"(addr));
}
__device__ __forceinline__ void ldmx4t(uint32_t* r, uint32_t addr) {
    asm volatile("ldmatrix.sync.aligned.m8n8.x4.trans.shared.b16 {%0,%1,%2,%3}, [%4];"
                 : "=r"(r[0]), "=r"(r[1]), "=r"(r[2]), "=r"(r[3]) : "r"(addr));
}
__device__ __forceinline__ void mma16816(float* c, const uint32_t* a,
                                         const uint32_t b0, const uint32_t b1) {
    asm volatile(
        "mma.sync.aligned.m16n8k16.row.col.f32.bf16.bf16.f32 "
        "{%0,%1,%2,%3}, {%4,%5,%6,%7}, {%8,%9}, {%0,%1,%2,%3};"
        : "+f"(c[0]), "+f"(c[1]), "+f"(c[2]), "+f"(c[3])
        : "r"(a[0]), "r"(a[1]), "r"(a[2]), "r"(a[3]), "r"(b0), "r"(b1));
}

// ---------------------------------------------------------------------------
// bg copy
// ---------------------------------------------------------------------------
__global__ void bg_copy_kernel(const float* __restrict__ Kbg,
                               const float* __restrict__ Vbg)
{
    int i = blockIdx.x * blockDim.x + threadIdx.x;
    const int n = BH * Lq * HDq;
    if (i >= n) return;
    int head = i / (Lq * HDq);
    int rem  = i - head * (Lq * HDq);
    int dst  = head * (LKV * HDq) + (Lq * HDq) + rem;
    g_K[dst] = ALPHA * Kbg[i];
    g_V[dst] = ALPHA * Vbg[i];
}

// ---------------------------------------------------------------------------
// hi/lo split helpers
// ---------------------------------------------------------------------------
__device__ __forceinline__ void cvt_hi_lo(float4 v, uint2& hi, uint2& lo)
{
    uint32_t x0 = __float_as_uint(v.x), x1 = __float_as_uint(v.y);
    uint32_t x2 = __float_as_uint(v.z), x3 = __float_as_uint(v.w);
    hi.x = __byte_perm(x0, x1, 0x7632);
    hi.y = __byte_perm(x2, x3, 0x7632);
    float l0 = v.x - __uint_as_float(x0 & 0xFFFF0000u);
    float l1 = v.y - __uint_as_float(x1 & 0xFFFF0000u);
    float l2 = v.z - __uint_as_float(x2 & 0xFFFF0000u);
    float l3 = v.w - __uint_as_float(x3 & 0xFFFF0000u);
    __nv_bfloat162 lp0 = __floats2bfloat162_rn(l0, l1);
    __nv_bfloat162 lp1 = __floats2bfloat162_rn(l2, l3);
    lo.x = *reinterpret_cast<uint32_t*>(&lp0);
    lo.y = *reinterpret_cast<uint32_t*>(&lp1);
}
__device__ __forceinline__ void pack_hi_lo(float x, float y, uint32_t& hi, uint32_t& lo)
{
    uint32_t xb = __float_as_uint(x), yb = __float_as_uint(y);
    hi = __byte_perm(xb, yb, 0x7632);
    float xl = x - __uint_as_float(xb & 0xFFFF0000u);
    float yl = y - __uint_as_float(yb & 0xFFFF0000u);
    __nv_bfloat162 t = __floats2bfloat162_rn(xl, yl);
    lo = *reinterpret_cast<uint32_t*>(&t);
}

// ---------------------------------------------------------------------------
// Tensor-core GEMM via mma.sync, DOUBLE-BUFFERED smem stages.
// C[4096,1280] = A[4096,1280] @ W[1280,1280]
// grid.z selects weight (fused QKV); fused=0 -> single W0 + bias epilogue.
// ---------------------------------------------------------------------------
#define BM 128
#define BN 128
#define BK 32
#define APAD 40
#define BPAD 136
#define A_ELE (BM * APAD)            // 5120
#define B_ELE (BK * BPAD)            // 4352
#define STAGE_ELE (2 * A_ELE + 2 * B_ELE)   // 18944 bf16
#define GEMM_SMEM_BYTES (2 * STAGE_ELE * 2) // 75776

__global__ __launch_bounds__(256)
void gemm_mma_kernel(const float* __restrict__ A,
                     const float* __restrict__ W0,
                     const float* __restrict__ W1,
                     const float* __restrict__ W2,
                     const float* __restrict__ bias,
                     float* __restrict__ C,
                     int fused)
{
    extern __shared__ __align__(16) __nv_bfloat16 smemb[];

    const int tid    = threadIdx.x;
    const int lane   = tid & 31;
    const int wid    = tid >> 5;
    const int warp_m = wid & 3;
    const int warp_n = wid >> 2;
    const int bm     = blockIdx.y * BM;
    const int bn     = blockIdx.x * BN;
    const int wsel   = blockIdx.z;
    const float* W   = (wsel == 0) ? W0 : (wsel == 1 ? W1 : W2);
    const int mode   = fused ? (1 + wsel) : 0;

    const uint32_t smem_base_u = smem_u32(smemb);

    float acc[2][8][4];
#pragma unroll
    for (int i = 0; i < 2; i++)
#pragma unroll
        for (int j = 0; j < 8; j++)
#pragma unroll
            for (int k = 0; k < 4; k++) acc[i][j][k] = 0.f;

    float4 a_pf[4], b_pf[4];
#pragma unroll
    for (int it = 0; it < 4; it++) {
        int i = it * 256 + tid;
        a_pf[it] = *(const float4*)(A + (size_t)(bm + (i >> 3)) * Dq + ((i & 7) << 2));
        b_pf[it] = *(const float4*)(W + (size_t)(i >> 5) * Dq + bn + ((i & 31) << 2));
    }

    // prologue: store chunk 0 into stage 0
    {
        __nv_bfloat16* Ah = smemb;
        __nv_bfloat16* Al = Ah + A_ELE;
        __nv_bfloat16* Bh = Al + A_ELE;
        __nv_bfloat16* Bl = Bh + B_ELE;
#pragma unroll
        for (int it = 0; it < 4; it++) {
            int i  = it * 256 + tid;
            int ar = i >> 3, ac = (i & 7) << 2;
            uint2 hi, lo;
            cvt_hi_lo(a_pf[it], hi, lo);
            *(uint2*)(Ah + ar * APAD + ac) = hi;
            *(uint2*)(Al + ar * APAD + ac) = lo;
            int br = i >> 5, bc = (i & 31) << 2;
            cvt_hi_lo(b_pf[it], hi, lo);
            *(uint2*)(Bh + br * BPAD + bc) = hi;
            *(uint2*)(Bl + br * BPAD + bc) = lo;
        }
    }
    __syncthreads();

    const int NCH = Dq / BK;   // 40
#pragma unroll 1
    for (int c = 0; c < NCH; c++) {
        const int st = c & 1;
        const uint32_t ah_u = smem_base_u + st * (STAGE_ELE * 2);
        const uint32_t al_u = ah_u + A_ELE * 2;
        const uint32_t bh_u = al_u + A_ELE * 2;
        const uint32_t bl_u = bh_u + B_ELE * 2;

        // issue next chunk's global loads early
        const bool have_next = (c + 1 < NCH);
        if (have_next) {
            int kk = (c + 1) * BK;
#pragma unroll
            for (int it = 0; it < 4; it++) {
                int i = it * 256 + tid;
                a_pf[it] = *(const float4*)(A + (size_t)(bm + (i >> 3)) * Dq + kk + ((i & 7) << 2));
                b_pf[it] = *(const float4*)(W + (size_t)(kk + (i >> 5)) * Dq + bn + ((i & 31) << 2));
            }
        }

        // compute on stage st
#pragma unroll
        for (int ks = 0; ks < 2; ks++) {
            uint32_t afh[2][4], afl[2][4];
#pragma unroll
            for (int mf = 0; mf < 2; mf++) {
                int row = warp_m * 32 + mf * 16 + (lane & 7) + ((lane >> 3) & 1) * 8;
                int col = ks * 16 + (lane >> 4) * 8;
                uint32_t off = (uint32_t)(row * APAD + col) * 2;
                ldmx4(afh[mf], ah_u + off);
                ldmx4(afl[mf], al_u + off);
            }
#pragma unroll
            for (int nfp = 0; nfp < 4; nfp++) {
                int krow = ks * 16 + (lane & 7) + ((lane >> 3) & 1) * 8;
                int ncol = warp_n * 64 + nfp * 16 + (lane >> 4) * 8;
                uint32_t off = (uint32_t)(krow * BPAD + ncol) * 2;
                uint32_t bfh[4], bfl[4];
                ldmx4t(bfh, bh_u + off);
                ldmx4t(bfl, bl_u + off);
#pragma unroll
                for (int mf = 0; mf < 2; mf++) {
                    float* c0 = acc[mf][nfp * 2];
                    float* c1 = acc[mf][nfp * 2 + 1];
                    mma16816(c0, afh[mf], bfh[0], bfh[1]);
                    mma16816(c1, afh[mf], bfh[2], bfh[3]);
                    mma16816(c0, afh[mf], bfl[0], bfl[1]);
                    mma16816(c1, afh[mf], bfl[2], bfl[3]);
                    mma16816(c0, afl[mf], bfh[0], bfh[1]);
                    mma16816(c1, afl[mf], bfh[2], bfh[3]);
                }
            }
        }

        // store next chunk into the other stage (no conflict with compute reads)
        if (have_next) {
            __nv_bfloat16* base = smemb + (st ^ 1) * STAGE_ELE;
            __nv_bfloat16* Ah = base;
            __nv_bfloat16* Al = Ah + A_ELE;
            __nv_bfloat16* Bh = Al + A_ELE;
            __nv_bfloat16* Bl = Bh + B_ELE;
#pragma unroll
            for (int it = 0; it < 4; it++) {
                int i  = it * 256 + tid;
                int ar = i >> 3, ac = (i & 7) << 2;
                uint2 hi, lo;
                cvt_hi_lo(a_pf[it], hi, lo);
                *(uint2*)(Ah + ar * APAD + ac) = hi;
                *(uint2*)(Al + ar * APAD + ac) = lo;
                int br = i >> 5, bc = (i & 31) << 2;
                cvt_hi_lo(b_pf[it], hi, lo);
                *(uint2*)(Bh + br * BPAD + bc) = hi;
                *(uint2*)(Bl + br * BPAD + bc) = lo;
            }
        }
        __syncthreads();
    }

    // epilogue
    const int group = lane >> 2;
    const int tg    = lane & 3;
#pragma unroll
    for (int mf = 0; mf < 2; mf++) {
#pragma unroll
        for (int nf = 0; nf < 8; nf++) {
            int col = bn + warp_n * 64 + nf * 8 + tg * 2;
#pragma unroll
            for (int half = 0; half < 2; half++) {
                int row = bm + warp_m * 32 + mf * 16 + group + half * 8;
                float v0 = acc[mf][nf][half * 2];
                float v1 = acc[mf][nf][half * 2 + 1];
                if (mode == 0) {
                    v0 += bias[col];
                    v1 += bias[col + 1];
                    *(float2*)(C + (size_t)row * Dq + col) = make_float2(v0, v1);
                } else {
                    int b  = row >> 10;
                    int l  = row & 1023;
                    int h  = col >> 6;
                    int hd = col & 63;
                    float2 v2 = make_float2(v0, v1);
                    if (mode == 1) {
                        *(float2*)(g_Q + (((size_t)(b * Hq + h)) * Lq + l) * HDq + hd) = v2;
                    } else if (mode == 2) {
                        *(float2*)(g_K + (((size_t)(b * Hq + h)) * LKV + l) * HDq + hd) = v2;
                    } else {
                        *(float2*)(g_V + (((size_t)(b * Hq + h)) * LKV + l) * HDq + hd) = v2;
                    }
                }
            }
        }
    }
}

// ---------------------------------------------------------------------------
// Tensor-core flash attention (unchanged from passing round 7)
// ---------------------------------------------------------------------------
#define PITCH 72

__global__ __launch_bounds__(256)
void attn_mma_kernel()
{
    __shared__ __align__(16) __nv_bfloat16 sm_t[4 * 64 * PITCH];

    const int head = blockIdx.y;
    const int qb   = blockIdx.x * 128;
    const int tid  = threadIdx.x;
    const int lane = tid & 31;
    const int warp = tid >> 5;

    __nv_bfloat16* Qh_s = sm_t;
    __nv_bfloat16* Ql_s = sm_t + 128 * PITCH;
    __nv_bfloat16* Kh_s = sm_t;
    __nv_bfloat16* Kl_s = sm_t + 64 * PITCH;
    __nv_bfloat16* Vh_s = sm_t + 2 * 64 * PITCH;
    __nv_bfloat16* Vl_s = sm_t + 3 * 64 * PITCH;
    const uint32_t qh_u = smem_u32(Qh_s);
    const uint32_t ql_u = smem_u32(Ql_s);
    const uint32_t kh_u = smem_u32(Kh_s);
    const uint32_t kl_u = smem_u32(Kl_s);
    const uint32_t vh_u = smem_u32(Vh_s);
    const uint32_t vl_u = smem_u32(Vl_s);

    const float* Qp = g_Q + ((size_t)head * Lq + qb) * HDq;
#pragma unroll
    for (int it = 0; it < 8; it++) {
        int i  = it * 256 + tid;
        int r  = i >> 4;
        int c4 = (i & 15) << 2;
        float4 v = *(const float4*)(Qp + r * 64 + c4);
        v.x *= 0.125f; v.y *= 0.125f; v.z *= 0.125f; v.w *= 0.125f;
        uint2 hi, lo;
        cvt_hi_lo(v, hi, lo);
        *(uint2*)(Qh_s + r * PITCH + c4) = hi;
        *(uint2*)(Ql_s + r * PITCH + c4) = lo;
    }
    __syncthreads();

    uint32_t qfh[4][4], qfl[4][4];
    {
        int arow = warp * 16 + (lane & 7) + ((lane >> 3) & 1) * 8;
#pragma unroll
        for (int ks = 0; ks < 4; ks++) {
            uint32_t off = (uint32_t)(arow * PITCH + ks * 16 + (lane >> 4) * 8) * 2;
            ldmx4(qfh[ks], qh_u + off);
            ldmx4(qfl[ks], ql_u + off);
        }
    }
    __syncthreads();

    float O[8][4];
#pragma unroll
    for (int i = 0; i < 8; i++)
#pragma unroll
        for (int j = 0; j < 4; j++) O[i][j] = 0.f;
    float m_r[2] = {-1e30f, -1e30f};
    float l_r[2] = {0.f, 0.f};

    const float* Kp = g_K + (size_t)head * LKV * HDq;
    const float* Vp = g_V + (size_t)head * LKV * HDq;

    float4 kpf[4], vpf[4];
#pragma unroll
    for (int it = 0; it < 4; it++) {
        int i  = it * 256 + tid;
        int r  = i >> 4;
        int c4 = (i & 15) << 2;
        kpf[it] = *(const float4*)(Kp + (size_t)r * 64 + c4);
        vpf[it] = *(const float4*)(Vp + (size_t)r * 64 + c4);
    }

    const int NKT = LKV / 64;   // 32
#pragma unroll 1
    for (int kt = 0; kt < NKT; kt++) {
#pragma unroll
        for (int it = 0; it < 4; it++) {
            int i  = it * 256 + tid;
            int r  = i >> 4;
            int c4 = (i & 15) << 2;
            uint2 hi, lo;
            cvt_hi_lo(kpf[it], hi, lo);
            *(uint2*)(Kh_s + r * PITCH + c4) = hi;
            *(uint2*)(Kl_s + r * PITCH + c4) = lo;
            cvt_hi_lo(vpf[it], hi, lo);
            *(uint2*)(Vh_s + r * PITCH + c4) = hi;
            *(uint2*)(Vl_s + r * PITCH + c4) = lo;
        }
        __syncthreads();

        if (kt + 1 < NKT) {
            const float* kn = Kp + (size_t)(kt + 1) * 64 * 64;
            const float* vn = Vp + (size_t)(kt + 1) * 64 * 64;
#pragma unroll
            for (int it = 0; it < 4; it++) {
                int i  = it * 256 + tid;
                int r  = i >> 4;
                int c4 = (i & 15) << 2;
                kpf[it] = *(const float4*)(kn + (size_t)r * 64 + c4);
                vpf[it] = *(const float4*)(vn + (size_t)r * 64 + c4);
            }
        }

        float c[8][4];
#pragma unroll
        for (int i = 0; i < 8; i++)
#pragma unroll
            for (int j = 0; j < 4; j++) c[i][j] = 0.f;

#pragma unroll
        for (int ks = 0; ks < 4; ks++) {
#pragma unroll
            for (int n16 = 0; n16 < 4; n16++) {
                int nrow = n16 * 16 + (lane & 7) + (lane >> 4) * 8;
                int kcol = ks * 16 + ((lane >> 3) & 1) * 8;
                uint32_t off = (uint32_t)(nrow * PITCH + kcol) * 2;
                uint32_t kh[4], kl[4];
                ldmx4(kh, kh_u + off);
                ldmx4(kl, kl_u + off);
                float* c0 = c[n16 * 2];
                float* c1 = c[n16 * 2 + 1];
                mma16816(c0, qfh[ks], kh[0], kh[1]);
                mma16816(c1, qfh[ks], kh[2], kh[3]);
                mma16816(c0, qfh[ks], kl[0], kl[1]);
                mma16816(c1, qfh[ks], kl[2], kl[3]);
                mma16816(c0, qfl[ks], kh[0], kh[1]);
                mma16816(c1, qfl[ks], kh[2], kh[3]);
            }
        }

#pragma unroll
        for (int h = 0; h < 2; h++) {
            float rm = c[0][2 * h];
#pragma unroll
            for (int nf = 0; nf < 8; nf++) {
                rm = fmaxf(rm, c[nf][2 * h]);
                rm = fmaxf(rm, c[nf][2 * h + 1]);
            }
            rm = fmaxf(rm, __shfl_xor_sync(0xffffffffu, rm, 1));
            rm = fmaxf(rm, __shfl_xor_sync(0xffffffffu, rm, 2));
            float mnew  = fmaxf(m_r[h], rm);
            float alpha = __expf(m_r[h] - mnew);
            float sum = 0.f;
#pragma unroll
            for (int nf = 0; nf < 8; nf++) {
                c[nf][2 * h]     = __expf(c[nf][2 * h] - mnew);
                c[nf][2 * h + 1] = __expf(c[nf][2 * h + 1] - mnew);
                sum += c[nf][2 * h] + c[nf][2 * h + 1];
            }
            sum += __shfl_xor_sync(0xffffffffu, sum, 1);
            sum += __shfl_xor_sync(0xffffffffu, sum, 2);
            l_r[h] = l_r[h] * alpha + sum;
            m_r[h] = mnew;
#pragma unroll
            for (int nf = 0; nf < 8; nf++) {
                O[nf][2 * h]     *= alpha;
                O[nf][2 * h + 1] *= alpha;
            }
        }

#pragma unroll
        for (int ks = 0; ks < 4; ks++) {
            uint32_t ph[4], pl[4];
            pack_hi_lo(c[2 * ks][0],     c[2 * ks][1],     ph[0], pl[0]);
            pack_hi_lo(c[2 * ks][2],     c[2 * ks][3],     ph[1], pl[1]);
            pack_hi_lo(c[2 * ks + 1][0], c[2 * ks + 1][1], ph[2], pl[2]);
            pack_hi_lo(c[2 * ks + 1][2], c[2 * ks + 1][3], ph[3], pl[3]);
#pragma unroll
            for (int nfp = 0; nfp < 4; nfp++) {
                int krow = ks * 16 + (lane & 7) + ((lane >> 3) & 1) * 8;
                int ncol = nfp * 16 + (lane >> 4) * 8;
                uint32_t off = (uint32_t)(krow * PITCH + ncol) * 2;
                uint32_t vh[4], vl[4];
                ldmx4t(vh, vh_u + off);
                ldmx4t(vl, vl_u + off);
                float* o0 = O[nfp * 2];
                float* o1 = O[nfp * 2 + 1];
                mma16816(o0, ph, vh[0], vh[1]);
                mma16816(o1, ph, vh[2], vh[3]);
                mma16816(o0, ph, vl[0], vl[1]);
                mma16816(o1, ph, vl[2], vl[3]);
                mma16816(o0, pl, vh[0], vh[1]);
                mma16816(o1, pl, vh[2], vh[3]);
            }
        }
        __syncthreads();
    }

    const int b = head / Hq;
    const int h = head - b * Hq;
    const int group = lane >> 2;
    const int tg    = lane & 3;
    float inv0 = 1.f / l_r[0];
    float inv1 = 1.f / l_r[1];
    int row0 = qb + warp * 16 + group;
    int row1 = row0 + 8;
#pragma unroll
    for (int nf = 0; nf < 8; nf++) {
        int col = h * HDq + nf * 8 + tg * 2;
        *(float2*)(g_ctx + (size_t)(b * Lq + row0) * Dq + col) =
            make_float2(O[nf][0] * inv0, O[nf][1] * inv0);
        *(float2*)(g_ctx + (size_t)(b * Lq + row1) * Dq + col) =
            make_float2(O[nf][2] * inv1, O[nf][3] * inv1);
    }
}

// ---------------------------------------------------------------------------
// Launch
// ---------------------------------------------------------------------------
extern "C" void kernel_launch(void* const* d_in, const int* in_sizes, int n_in,
                              void* d_out, int out_size)
{
    const float* X   = (const float*)d_in[0];
    const float* Kbg = (const float*)d_in[1];
    const float* Vbg = (const float*)d_in[2];
    const float* Wq  = (const float*)d_in[3];
    const float* Wk  = (const float*)d_in[4];
    const float* Wv  = (const float*)d_in[5];
    const float* Wo  = (const float*)d_in[6];
    const float* bo  = (const float*)d_in[7];
    float* out = (float*)d_out;

    static bool init_done = false;
    static float* ctx_ptr = nullptr;
    if (!init_done) {
        cudaFuncSetAttribute(gemm_mma_kernel,
                             cudaFuncAttributeMaxDynamicSharedMemorySize,
                             GEMM_SMEM_BYTES);
        cudaGetSymbolAddress((void**)&ctx_ptr, g_ctx);
        init_done = true;
    }

    {
        int n = BH * Lq * HDq;
        bg_copy_kernel<<<(n + 255) / 256, 256>>>(Kbg, Vbg);
    }

    // Fused QKV projections: grid.z picks weight + destination
    {
        dim3 qkv_grid(Dq / BN, Mrows / BM, 3);   // (10, 32, 3)
        gemm_mma_kernel<<<qkv_grid, 256, GEMM_SMEM_BYTES>>>(
            X, Wq, Wk, Wv, nullptr, nullptr, 1);
    }

    {
        dim3 agrid(Lq / 128, BH);                // (8, 80)
        attn_mma_kernel<<<agrid, 256>>>();
    }

    // Output projection + bias
    {
        dim3 ogrid(Dq / BN, Mrows / BM, 1);      // (10, 32, 1)
        gemm_mma_kernel<<<ogrid, 256, GEMM_SMEM_BYTES>>>(
            ctx_ptr, Wo, nullptr, nullptr, bo, out, 0);
    }
}